// round 9
// baseline (speedup 1.0000x reference)
#include <cuda_runtime.h>
#include <cuda_bf16.h>
#include <cstdint>

// Problem constants
#define BB 8
#define SS 1024
#define DD 768
#define HH 12
#define HD 64

// Scratch: projected q,k (B,H,S,HD), v transposed (B,H,HD,S), rel_attn
__device__ float g_q[BB * HH * SS * HD];      // 24 MB
__device__ float g_k[BB * HH * SS * HD];      // 24 MB
__device__ float g_vT[BB * HH * HD * SS];     // 24 MB (d-major for PV B-operand)
__device__ float g_rel[BB * SS * SS];         // 32 MB

// ---- tf32 mma helpers ------------------------------------------------------
__device__ __forceinline__ uint32_t f2tf(float f) {
    uint32_t r;
    asm("cvt.rna.tf32.f32 %0, %1;" : "=r"(r) : "f"(f));
    return r;
}
__device__ __forceinline__ void sts_tf32(uint32_t* p, float4 v) {
    uint4 u;
    u.x = f2tf(v.x); u.y = f2tf(v.y); u.z = f2tf(v.z); u.w = f2tf(v.w);
    *(uint4*)p = u;
}
__device__ __forceinline__ void mma8(float* d, const uint32_t* a, const uint32_t* b) {
    asm("mma.sync.aligned.m16n8k8.row.col.f32.tf32.tf32.f32 "
        "{%0,%1,%2,%3}, {%4,%5,%6,%7}, {%8,%9}, {%0,%1,%2,%3};"
        : "+f"(d[0]), "+f"(d[1]), "+f"(d[2]), "+f"(d[3])
        : "r"(a[0]), "r"(a[1]), "r"(a[2]), "r"(a[3]), "r"(b[0]), "r"(b[1]));
}

// ---------------------------------------------------------------------------
// Projection GEMM (tf32 MMA): Y[i,j] = sum_k X[i,k] * W[j,k] + b[j]
// Block 128x128, BK=16, 8 warps (2x4), warp tile 64x32.
// vtFlag=0: write (B,H,S,HD).  vtFlag=1: write transposed (B,H,HD,S).
// ---------------------------------------------------------------------------
__global__ __launch_bounds__(256) void proj_mma(
    const float* __restrict__ X, const float* __restrict__ W,
    const float* __restrict__ bias, float* __restrict__ out, int vtFlag)
{
    __shared__ uint32_t As[128][20];   // stride 20 == 4 mod 32: frag LDS conflict-free
    __shared__ uint32_t Bs[128][20];

    const int t    = threadIdx.x;
    const int lane = t & 31;
    const int wid  = t >> 5;
    const int grp  = lane >> 2;
    const int tig  = lane & 3;
    const int wm   = wid >> 2;         // 0..1
    const int wn   = wid & 3;          // 0..3
    const int bm   = blockIdx.y * 128;
    const int bn   = blockIdx.x * 128;

    float acc[4][4][4];
#pragma unroll
    for (int mt = 0; mt < 4; mt++)
#pragma unroll
        for (int nt = 0; nt < 4; nt++)
#pragma unroll
            for (int r = 0; r < 4; r++) acc[mt][nt][r] = 0.f;

    const int lr = t >> 2;            // 0..63
    const int lc = (t & 3) * 4;       // 0,4,8,12
    const float* xp0 = X + (size_t)(bm + lr) * DD + lc;
    const float* xp1 = xp0 + (size_t)64 * DD;
    const float* wp0 = W + (size_t)(bn + lr) * DD + lc;
    const float* wp1 = wp0 + (size_t)64 * DD;

    float4 xa0 = *(const float4*)xp0;
    float4 xa1 = *(const float4*)xp1;
    float4 wb0 = *(const float4*)wp0;
    float4 wb1 = *(const float4*)wp1;

    for (int k0 = 0; k0 < DD; k0 += 16) {
        sts_tf32(&As[lr][lc],      xa0);
        sts_tf32(&As[lr + 64][lc], xa1);
        sts_tf32(&Bs[lr][lc],      wb0);
        sts_tf32(&Bs[lr + 64][lc], wb1);
        __syncthreads();

        if (k0 + 16 < DD) {
            xa0 = *(const float4*)(xp0 + k0 + 16);
            xa1 = *(const float4*)(xp1 + k0 + 16);
            wb0 = *(const float4*)(wp0 + k0 + 16);
            wb1 = *(const float4*)(wp1 + k0 + 16);
        }

#pragma unroll
        for (int ks = 0; ks < 16; ks += 8) {
            uint32_t a[4][4], bq[4][2];
#pragma unroll
            for (int mt = 0; mt < 4; mt++) {
                const int m = wm * 64 + mt * 16;
                a[mt][0] = As[m + grp][ks + tig];
                a[mt][1] = As[m + grp + 8][ks + tig];
                a[mt][2] = As[m + grp][ks + tig + 4];
                a[mt][3] = As[m + grp + 8][ks + tig + 4];
            }
#pragma unroll
            for (int nt = 0; nt < 4; nt++) {
                const int n = wn * 32 + nt * 8;
                bq[nt][0] = Bs[n + grp][ks + tig];
                bq[nt][1] = Bs[n + grp][ks + tig + 4];
            }
#pragma unroll
            for (int mt = 0; mt < 4; mt++)
#pragma unroll
                for (int nt = 0; nt < 4; nt++)
                    mma8(acc[mt][nt], a[mt], bq[nt]);
        }
        __syncthreads();
    }

#pragma unroll
    for (int mt = 0; mt < 4; mt++) {
        const int row0 = bm + wm * 64 + mt * 16 + grp;
#pragma unroll
        for (int nt = 0; nt < 4; nt++) {
            const int col = bn + wn * 32 + nt * 8 + 2 * tig;
            const int h = col >> 6, d = col & 63;
            const float bi0 = bias[col], bi1 = bias[col + 1];
#pragma unroll
            for (int rr = 0; rr < 2; rr++) {
                const int row = row0 + 8 * rr;
                const int b = row >> 10, s = row & 1023;
                const float v0 = acc[mt][nt][2 * rr]     + bi0;
                const float v1 = acc[mt][nt][2 * rr + 1] + bi1;
                if (!vtFlag) {
                    *(float2*)&out[(((size_t)b * HH + h) * SS + s) * HD + d] =
                        make_float2(v0, v1);
                } else {
                    out[(((size_t)b * HH + h) * HD + d)     * SS + s] = v0;
                    out[(((size_t)b * HH + h) * HD + d + 1) * SS + s] = v1;
                }
            }
        }
    }
}

// ---------------------------------------------------------------------------
// rel_attn = softmax over k of (mask ? rel : -1e4).  (head-independent)
// ---------------------------------------------------------------------------
__global__ __launch_bounds__(256) void rel_softmax_kernel(
    const float* __restrict__ rel, const unsigned int* __restrict__ mask,
    float* __restrict__ outr)
{
    const int row = blockIdx.x;
    const float* r        = rel  + (size_t)row * SS;
    const unsigned int* m = mask + (size_t)row * SS;
    float* o              = outr + (size_t)row * SS;

    __shared__ float redmax[8], redsum[8];
    const int t = threadIdx.x;

    float v[4];
    float mx = -3.4e38f;
#pragma unroll
    for (int i = 0; i < 4; i++) {
        const int c = i * 256 + t;
        v[i] = m[c] ? r[c] : -1e4f;
        mx = fmaxf(mx, v[i]);
    }
#pragma unroll
    for (int o2 = 16; o2; o2 >>= 1) mx = fmaxf(mx, __shfl_xor_sync(0xffffffffu, mx, o2));
    if ((t & 31) == 0) redmax[t >> 5] = mx;
    __syncthreads();
    mx = redmax[0];
#pragma unroll
    for (int w = 1; w < 8; w++) mx = fmaxf(mx, redmax[w]);

    float sum = 0.f;
#pragma unroll
    for (int i = 0; i < 4; i++) {
        v[i] = __expf(v[i] - mx);
        sum += v[i];
    }
#pragma unroll
    for (int o2 = 16; o2; o2 >>= 1) sum += __shfl_xor_sync(0xffffffffu, sum, o2);
    if ((t & 31) == 0) redsum[t >> 5] = sum;
    __syncthreads();
    sum = 0.f;
#pragma unroll
    for (int w = 0; w < 8; w++) sum += redsum[w];
    const float inv = 1.f / sum;

#pragma unroll
    for (int i = 0; i < 4; i++) {
        const int c = i * 256 + t;
        o[c] = v[i] * inv;
    }
}

// ---------------------------------------------------------------------------
// Fused attention (tf32 MMA, flash-style recompute).
// One block per (b, h, 128-q tile), 8 warps.
// Pass 1: S=QK^T tiles -> masked exp row sums only (nothing stored).
// Pass 2: recompute S -> e -> p = c0*e/l + l1*rel -> write prob; stage P,
//         accumulate O = P @ V.
// SMEM: Qs[128][68] + Ks[128][68] + Ps[128][132] + Vs[64][132] = 167 KB.
// ---------------------------------------------------------------------------
#define FS  68
#define PSTR 132
#define AT_SMEM ((2 * 128 * FS + 128 * PSTR + 64 * PSTR) * 4)

__global__ __launch_bounds__(256) void attn_fused(
    const float* __restrict__ qg, const float* __restrict__ kg,
    const float* __restrict__ vT, const unsigned int* __restrict__ mask,
    const float* __restrict__ relattn, const float* __restrict__ l1p,
    float* __restrict__ out, float* __restrict__ prob)
{
    extern __shared__ uint32_t smm[];
    uint32_t (*Qs)[FS]   = (uint32_t(*)[FS])smm;
    uint32_t (*Ks)[FS]   = (uint32_t(*)[FS])(smm + 128 * FS);
    uint32_t (*Ps)[PSTR] = (uint32_t(*)[PSTR])(smm + 2 * 128 * FS);
    uint32_t (*Vs)[PSTR] = (uint32_t(*)[PSTR])(smm + 2 * 128 * FS + 128 * PSTR);
    __shared__ float lsum_s[128];
    __shared__ float invl_s[128];

    const int t    = threadIdx.x;
    const int lane = t & 31;
    const int wid  = t >> 5;
    const int grp  = lane >> 2;
    const int tig  = lane & 3;
    const int wm   = wid >> 2;
    const int wn   = wid & 3;
    const int qt = blockIdx.x, h = blockIdx.y, b = blockIdx.z;
    const int bh = b * HH + h;
    const int qbase = qt * 128;

    const float l1 = *l1p;
    const float c0 = 1.f - l1;

    if (t < 128) lsum_s[t] = 0.f;

    // stage Q (128 x 64) as tf32 — once
    const float* Qg = qg + ((size_t)bh * SS + qbase) * HD;
#pragma unroll
    for (int i = 0; i < 8; i++) {
        const int f = t + 256 * i;
        const int r = f >> 4, c4 = (f & 15) * 4;
        sts_tf32(&Qs[r][c4], *(const float4*)(Qg + (size_t)r * HD + c4));
    }

    const float* Kg = kg + (size_t)bh * SS * HD;
    float rs[4][2];
#pragma unroll
    for (int mt = 0; mt < 4; mt++) { rs[mt][0] = 0.f; rs[mt][1] = 0.f; }

    // ---------------- pass 1: row sums ----------------
#pragma unroll 1
    for (int kt = 0; kt < 8; kt++) {
        __syncthreads();   // covers Q stage + lsum_s init at kt=0; prior Ks reads
#pragma unroll
        for (int i = 0; i < 8; i++) {
            const int f = t + 256 * i;
            const int r = f >> 4, c4 = (f & 15) * 4;
            sts_tf32(&Ks[r][c4],
                     *(const float4*)(Kg + (size_t)(kt * 128 + r) * HD + c4));
        }
        __syncthreads();

        float acc[4][4][4];
#pragma unroll
        for (int mt = 0; mt < 4; mt++)
#pragma unroll
            for (int nt = 0; nt < 4; nt++)
#pragma unroll
                for (int r = 0; r < 4; r++) acc[mt][nt][r] = 0.f;

#pragma unroll
        for (int k8 = 0; k8 < 8; k8++) {
            const int ks = 8 * k8;
            uint32_t a[4][4], bq[4][2];
#pragma unroll
            for (int mt = 0; mt < 4; mt++) {
                const int m = wm * 64 + mt * 16;
                a[mt][0] = Qs[m + grp][ks + tig];
                a[mt][1] = Qs[m + grp + 8][ks + tig];
                a[mt][2] = Qs[m + grp][ks + tig + 4];
                a[mt][3] = Qs[m + grp + 8][ks + tig + 4];
            }
#pragma unroll
            for (int nt = 0; nt < 4; nt++) {
                const int n = wn * 32 + nt * 8;
                bq[nt][0] = Ks[n + grp][ks + tig];
                bq[nt][1] = Ks[n + grp][ks + tig + 4];
            }
#pragma unroll
            for (int mt = 0; mt < 4; mt++)
#pragma unroll
                for (int nt = 0; nt < 4; nt++)
                    mma8(acc[mt][nt], a[mt], bq[nt]);
        }

#pragma unroll
        for (int mt = 0; mt < 4; mt++) {
            const int q0 = qbase + wm * 64 + mt * 16 + grp;
#pragma unroll
            for (int nt = 0; nt < 4; nt++) {
                const int c = kt * 128 + wn * 32 + nt * 8 + 2 * tig;
                const uint2 ma = *(const uint2*)&mask[((size_t)b * SS + q0) * SS + c];
                const uint2 mb = *(const uint2*)&mask[((size_t)b * SS + q0 + 8) * SS + c];
                rs[mt][0] += (ma.x ? 0.f : __expf(acc[mt][nt][0] * 0.125f))
                           + (ma.y ? 0.f : __expf(acc[mt][nt][1] * 0.125f));
                rs[mt][1] += (mb.x ? 0.f : __expf(acc[mt][nt][2] * 0.125f))
                           + (mb.y ? 0.f : __expf(acc[mt][nt][3] * 0.125f));
            }
        }
    }

    // reduce row sums across quads + n-warps
#pragma unroll
    for (int mt = 0; mt < 4; mt++)
#pragma unroll
        for (int rr = 0; rr < 2; rr++) {
            float v = rs[mt][rr];
            v += __shfl_xor_sync(0xffffffffu, v, 1);
            v += __shfl_xor_sync(0xffffffffu, v, 2);
            if (tig == 0)
                atomicAdd(&lsum_s[wm * 64 + mt * 16 + grp + 8 * rr], v);
        }
    __syncthreads();
    if (t < 128) invl_s[t] = 1.f / lsum_s[t];

    // ---------------- pass 2: blend + prob + PV ----------------
    float oacc[4][2][4];
#pragma unroll
    for (int mt = 0; mt < 4; mt++)
#pragma unroll
        for (int nt = 0; nt < 2; nt++)
#pragma unroll
            for (int r = 0; r < 4; r++) oacc[mt][nt][r] = 0.f;

#pragma unroll 1
    for (int kt = 0; kt < 8; kt++) {
        __syncthreads();   // prev PV reads of Ps/Vs done; invl_s visible at kt=0
        // stage K tile (128 keys x 64 d) and V tile (64 d x 128 keys)
#pragma unroll
        for (int i = 0; i < 8; i++) {
            const int f = t + 256 * i;
            const int r = f >> 4, c4 = (f & 15) * 4;
            sts_tf32(&Ks[r][c4],
                     *(const float4*)(Kg + (size_t)(kt * 128 + r) * HD + c4));
        }
#pragma unroll
        for (int i = 0; i < 8; i++) {
            const int f = t + 256 * i;
            const int d = f >> 5, c4 = (f & 31) * 4;
            sts_tf32(&Vs[d][c4],
                     *(const float4*)(vT + ((size_t)bh * HD + d) * SS + kt * 128 + c4));
        }
        __syncthreads();

        float acc[4][4][4];
#pragma unroll
        for (int mt = 0; mt < 4; mt++)
#pragma unroll
            for (int nt = 0; nt < 4; nt++)
#pragma unroll
                for (int r = 0; r < 4; r++) acc[mt][nt][r] = 0.f;

#pragma unroll
        for (int k8 = 0; k8 < 8; k8++) {
            const int ks = 8 * k8;
            uint32_t a[4][4], bq[4][2];
#pragma unroll
            for (int mt = 0; mt < 4; mt++) {
                const int m = wm * 64 + mt * 16;
                a[mt][0] = Qs[m + grp][ks + tig];
                a[mt][1] = Qs[m + grp + 8][ks + tig];
                a[mt][2] = Qs[m + grp][ks + tig + 4];
                a[mt][3] = Qs[m + grp + 8][ks + tig + 4];
            }
#pragma unroll
            for (int nt = 0; nt < 4; nt++) {
                const int n = wn * 32 + nt * 8;
                bq[nt][0] = Ks[n + grp][ks + tig];
                bq[nt][1] = Ks[n + grp][ks + tig + 4];
            }
#pragma unroll
            for (int mt = 0; mt < 4; mt++)
#pragma unroll
                for (int nt = 0; nt < 4; nt++)
                    mma8(acc[mt][nt], a[mt], bq[nt]);
        }

        // epilogue: e -> p, write prob, stage P fragments
#pragma unroll
        for (int mt = 0; mt < 4; mt++) {
            const int ql0 = wm * 64 + mt * 16 + grp;
            const int q0  = qbase + ql0;
            const float iv0 = invl_s[ql0];
            const float iv1 = invl_s[ql0 + 8];
#pragma unroll
            for (int nt = 0; nt < 4; nt++) {
                const int cl = wn * 32 + nt * 8 + 2 * tig;  // key within tile
                const int c  = kt * 128 + cl;
                const uint2  ma = *(const uint2*)&mask[((size_t)b * SS + q0) * SS + c];
                const uint2  mb = *(const uint2*)&mask[((size_t)b * SS + q0 + 8) * SS + c];
                const float2 ra = *(const float2*)&relattn[((size_t)b * SS + q0) * SS + c];
                const float2 rb = *(const float2*)&relattn[((size_t)b * SS + q0 + 8) * SS + c];
                const float e00 = ma.x ? 0.f : __expf(acc[mt][nt][0] * 0.125f);
                const float e01 = ma.y ? 0.f : __expf(acc[mt][nt][1] * 0.125f);
                const float e10 = mb.x ? 0.f : __expf(acc[mt][nt][2] * 0.125f);
                const float e11 = mb.y ? 0.f : __expf(acc[mt][nt][3] * 0.125f);
                const float p00 = c0 * e00 * iv0 + l1 * ra.x;
                const float p01 = c0 * e01 * iv0 + l1 * ra.y;
                const float p10 = c0 * e10 * iv1 + l1 * rb.x;
                const float p11 = c0 * e11 * iv1 + l1 * rb.y;
                *(float2*)&prob[((size_t)bh * SS + q0) * SS + c]     = make_float2(p00, p01);
                *(float2*)&prob[((size_t)bh * SS + q0 + 8) * SS + c] = make_float2(p10, p11);
                Ps[ql0][cl]         = f2tf(p00);
                Ps[ql0][cl + 1]     = f2tf(p01);
                Ps[ql0 + 8][cl]     = f2tf(p10);
                Ps[ql0 + 8][cl + 1] = f2tf(p11);
            }
        }
        __syncthreads();

        // PV MMA: O[128 q][64 d] += P[128][128] @ V^T[64][128]
#pragma unroll
        for (int k8 = 0; k8 < 16; k8++) {
            const int ks = 8 * k8;
            uint32_t a[4][4], bq[2][2];
#pragma unroll
            for (int mt = 0; mt < 4; mt++) {
                const int m = wm * 64 + mt * 16;
                a[mt][0] = Ps[m + grp][ks + tig];
                a[mt][1] = Ps[m + grp + 8][ks + tig];
                a[mt][2] = Ps[m + grp][ks + tig + 4];
                a[mt][3] = Ps[m + grp + 8][ks + tig + 4];
            }
#pragma unroll
            for (int nt = 0; nt < 2; nt++) {
                const int n = wn * 16 + nt * 8;
                bq[nt][0] = Vs[n + grp][ks + tig];
                bq[nt][1] = Vs[n + grp][ks + tig + 4];
            }
#pragma unroll
            for (int mt = 0; mt < 4; mt++)
#pragma unroll
                for (int nt = 0; nt < 2; nt++)
                    mma8(oacc[mt][nt], a[mt], bq[nt]);
        }
    }

#pragma unroll
    for (int mt = 0; mt < 4; mt++) {
        const int q0 = qbase + wm * 64 + mt * 16 + grp;
#pragma unroll
        for (int nt = 0; nt < 2; nt++) {
            const int d0 = wn * 16 + nt * 8 + 2 * tig;
            *(float2*)&out[((size_t)b * SS + q0) * DD + h * HD + d0] =
                make_float2(oacc[mt][nt][0], oacc[mt][nt][1]);
            *(float2*)&out[((size_t)b * SS + q0 + 8) * DD + h * HD + d0] =
                make_float2(oacc[mt][nt][2], oacc[mt][nt][3]);
        }
    }
}

// ---------------------------------------------------------------------------
extern "C" void kernel_launch(void* const* d_in, const int* in_sizes, int n_in,
                              void* d_out, int out_size)
{
    const float* query = (const float*)d_in[0];
    const float* key_t = (const float*)d_in[1];
    const float* value = (const float*)d_in[2];
    const float* rel   = (const float*)d_in[3];
    const unsigned int* mask = (const unsigned int*)d_in[4];
    const float* l1    = (const float*)d_in[5];
    const float* Wq = (const float*)d_in[6];
    const float* bq = (const float*)d_in[7];
    const float* Wk = (const float*)d_in[8];
    const float* bk = (const float*)d_in[9];
    const float* Wv = (const float*)d_in[10];
    const float* bv = (const float*)d_in[11];

    float* out  = (float*)d_out;
    float* prob = out + (size_t)BB * SS * DD;   // tuple layout: out, then prob_attn

    float *pq, *pk, *pvT, *prel;
    cudaGetSymbolAddress((void**)&pq,   g_q);
    cudaGetSymbolAddress((void**)&pk,   g_k);
    cudaGetSymbolAddress((void**)&pvT,  g_vT);
    cudaGetSymbolAddress((void**)&prel, g_rel);

    dim3 pg(DD / 128, (BB * SS) / 128);
    proj_mma<<<pg, 256>>>(query, Wq, bq, pq,  0);
    proj_mma<<<pg, 256>>>(key_t, Wk, bk, pk,  0);
    proj_mma<<<pg, 256>>>(value, Wv, bv, pvT, 1);

    rel_softmax_kernel<<<BB * SS, 256>>>(rel, mask, prel);

    cudaFuncSetAttribute(attn_fused,
                         cudaFuncAttributeMaxDynamicSharedMemorySize, AT_SMEM);
    attn_fused<<<dim3(8, HH, BB), 256, AT_SMEM>>>(
        pq, pk, pvT, mask, prel, l1, out, prob);
}

// round 10
// speedup vs baseline: 1.5167x; 1.5167x over previous
#include <cuda_runtime.h>
#include <cuda_fp16.h>
#include <cstdint>

// Problem constants
#define BB 8
#define SS 1024
#define DD 768
#define HH 12
#define HD 64

// Scratch (fp16): projected q,k (B,H,S,HD), v transposed (B,H,HD,S),
// e-scratch (B,H,S,S); fp32: rel_attn (B,S,S), row sums.
__device__ __half g_q[BB * HH * SS * HD];      // 12 MB
__device__ __half g_k[BB * HH * SS * HD];      // 12 MB
__device__ __half g_vT[BB * HH * HD * SS];     // 12 MB
__device__ __half g_e[(size_t)BB * HH * SS * SS];  // 201 MB
__device__ float  g_rel[BB * SS * SS];         // 32 MB
__device__ float  g_l[BB * HH * SS];           // 384 KB

// ---- fp16 mma helpers ------------------------------------------------------
__device__ __forceinline__ uint32_t pack_h2(float a, float b) {
    __half2 h = __floats2half2_rn(a, b);
    return *(uint32_t*)&h;
}
__device__ __forceinline__ uint2 pack2_h2(float4 v) {
    return make_uint2(pack_h2(v.x, v.y), pack_h2(v.z, v.w));
}
__device__ __forceinline__ float2 unpack_h2(uint32_t u) {
    __half2 h = *(__half2*)&u;
    return __half22float2(h);
}
// D(f32) += A(f16) * B(f16) : m16n8k16
__device__ __forceinline__ void mma16(float* d, const uint32_t* a, const uint32_t* b) {
    asm("mma.sync.aligned.m16n8k16.row.col.f32.f16.f16.f32 "
        "{%0,%1,%2,%3}, {%4,%5,%6,%7}, {%8,%9}, {%0,%1,%2,%3};"
        : "+f"(d[0]), "+f"(d[1]), "+f"(d[2]), "+f"(d[3])
        : "r"(a[0]), "r"(a[1]), "r"(a[2]), "r"(a[3]), "r"(b[0]), "r"(b[1]));
}

// ---------------------------------------------------------------------------
// Projection GEMM (fp16 MMA): Y[i,j] = sum_k X[i,k] * W[j,k] + b[j]
// Block 128x128, BK=16 (one k16 step), 8 warps (2x4), warp tile 64x32.
// vtFlag=0: write half (B,H,S,HD).  vtFlag=1: write half (B,H,HD,S).
// ---------------------------------------------------------------------------
__global__ __launch_bounds__(256) void proj_mma(
    const float* __restrict__ X, const float* __restrict__ W,
    const float* __restrict__ bias, __half* __restrict__ out, int vtFlag)
{
    __shared__ uint32_t As[128][12];   // half2 units: 8 data + 4 pad (stride%32==12 -> frag-safe)
    __shared__ uint32_t Bs[128][12];

    const int t    = threadIdx.x;
    const int lane = t & 31;
    const int wid  = t >> 5;
    const int grp  = lane >> 2;
    const int tig  = lane & 3;
    const int wm   = wid >> 2;         // 0..1
    const int wn   = wid & 3;          // 0..3
    const int bm   = blockIdx.y * 128;
    const int bn   = blockIdx.x * 128;

    float acc[4][4][4];
#pragma unroll
    for (int mt = 0; mt < 4; mt++)
#pragma unroll
        for (int nt = 0; nt < 4; nt++)
#pragma unroll
            for (int r = 0; r < 4; r++) acc[mt][nt][r] = 0.f;

    const int lr  = t >> 2;            // 0..63
    const int lc  = (t & 3) * 4;       // 0,4,8,12
    const int lc2 = lc >> 1;           // half2 col
    const float* xp0 = X + (size_t)(bm + lr) * DD + lc;
    const float* xp1 = xp0 + (size_t)64 * DD;
    const float* wp0 = W + (size_t)(bn + lr) * DD + lc;
    const float* wp1 = wp0 + (size_t)64 * DD;

    float4 xa0 = *(const float4*)xp0;
    float4 xa1 = *(const float4*)xp1;
    float4 wb0 = *(const float4*)wp0;
    float4 wb1 = *(const float4*)wp1;

    for (int k0 = 0; k0 < DD; k0 += 16) {
        *(uint2*)&As[lr][lc2]      = pack2_h2(xa0);
        *(uint2*)&As[lr + 64][lc2] = pack2_h2(xa1);
        *(uint2*)&Bs[lr][lc2]      = pack2_h2(wb0);
        *(uint2*)&Bs[lr + 64][lc2] = pack2_h2(wb1);
        __syncthreads();

        if (k0 + 16 < DD) {
            xa0 = *(const float4*)(xp0 + k0 + 16);
            xa1 = *(const float4*)(xp1 + k0 + 16);
            wb0 = *(const float4*)(wp0 + k0 + 16);
            wb1 = *(const float4*)(wp1 + k0 + 16);
        }

        uint32_t a[4][4], bq[4][2];
#pragma unroll
        for (int mt = 0; mt < 4; mt++) {
            const int m = wm * 64 + mt * 16;
            a[mt][0] = As[m + grp][tig];
            a[mt][1] = As[m + grp + 8][tig];
            a[mt][2] = As[m + grp][tig + 4];
            a[mt][3] = As[m + grp + 8][tig + 4];
        }
#pragma unroll
        for (int nt = 0; nt < 4; nt++) {
            const int n = wn * 32 + nt * 8;
            bq[nt][0] = Bs[n + grp][tig];
            bq[nt][1] = Bs[n + grp][tig + 4];
        }
#pragma unroll
        for (int mt = 0; mt < 4; mt++)
#pragma unroll
            for (int nt = 0; nt < 4; nt++)
                mma16(acc[mt][nt], a[mt], bq[nt]);
        __syncthreads();
    }

#pragma unroll
    for (int mt = 0; mt < 4; mt++) {
        const int row0 = bm + wm * 64 + mt * 16 + grp;
#pragma unroll
        for (int nt = 0; nt < 4; nt++) {
            const int col = bn + wn * 32 + nt * 8 + 2 * tig;
            const int h = col >> 6, d = col & 63;
            const float bi0 = bias[col], bi1 = bias[col + 1];
#pragma unroll
            for (int rr = 0; rr < 2; rr++) {
                const int row = row0 + 8 * rr;
                const int b = row >> 10, s = row & 1023;
                const float v0 = acc[mt][nt][2 * rr]     + bi0;
                const float v1 = acc[mt][nt][2 * rr + 1] + bi1;
                if (!vtFlag) {
                    *(uint32_t*)&out[(((size_t)b * HH + h) * SS + s) * HD + d] =
                        pack_h2(v0, v1);
                } else {
                    out[(((size_t)b * HH + h) * HD + d)     * SS + s] = __float2half(v0);
                    out[(((size_t)b * HH + h) * HD + d + 1) * SS + s] = __float2half(v1);
                }
            }
        }
    }
}

// ---------------------------------------------------------------------------
// rel_attn = softmax over k of (mask ? rel : -1e4).  (head-independent)
// ---------------------------------------------------------------------------
__global__ __launch_bounds__(256) void rel_softmax_kernel(
    const float* __restrict__ rel, const unsigned int* __restrict__ mask,
    float* __restrict__ outr)
{
    const int row = blockIdx.x;
    const float* r        = rel  + (size_t)row * SS;
    const unsigned int* m = mask + (size_t)row * SS;
    float* o              = outr + (size_t)row * SS;

    __shared__ float redmax[8], redsum[8];
    const int t = threadIdx.x;

    float v[4];
    float mx = -3.4e38f;
#pragma unroll
    for (int i = 0; i < 4; i++) {
        const int c = i * 256 + t;
        v[i] = m[c] ? r[c] : -1e4f;
        mx = fmaxf(mx, v[i]);
    }
#pragma unroll
    for (int o2 = 16; o2; o2 >>= 1) mx = fmaxf(mx, __shfl_xor_sync(0xffffffffu, mx, o2));
    if ((t & 31) == 0) redmax[t >> 5] = mx;
    __syncthreads();
    mx = redmax[0];
#pragma unroll
    for (int w = 1; w < 8; w++) mx = fmaxf(mx, redmax[w]);

    float sum = 0.f;
#pragma unroll
    for (int i = 0; i < 4; i++) {
        v[i] = __expf(v[i] - mx);
        sum += v[i];
    }
#pragma unroll
    for (int o2 = 16; o2; o2 >>= 1) sum += __shfl_xor_sync(0xffffffffu, sum, o2);
    if ((t & 31) == 0) redsum[t >> 5] = sum;
    __syncthreads();
    sum = 0.f;
#pragma unroll
    for (int w = 0; w < 8; w++) sum += redsum[w];
    const float inv = 1.f / sum;

#pragma unroll
    for (int i = 0; i < 4; i++) {
        const int c = i * 256 + t;
        o[c] = v[i] * inv;
    }
}

// ---------------------------------------------------------------------------
// QK (fp16 MMA): one block per (b, h, 128-q tile).
// e = mask ? 0 : exp((q.k)/8)  (no max shift: |s| <~ 2); e -> g_e (fp16);
// row sums -> g_l (fp32).
// SMEM: Qs[128][36] + Ks[128][36] half2-units = 36.9 KB.
// ---------------------------------------------------------------------------
#define QKS 36
#define QK_SMEM (2 * 128 * QKS * 4)

__global__ __launch_bounds__(256) void qk_mma(
    const __half* __restrict__ qg, const __half* __restrict__ kg,
    const unsigned int* __restrict__ mask,
    __half* __restrict__ eg, float* __restrict__ lsum)
{
    extern __shared__ uint32_t qsm[];
    uint32_t (*Qs)[QKS] = (uint32_t(*)[QKS])qsm;
    uint32_t (*Ks)[QKS] = (uint32_t(*)[QKS])(qsm + 128 * QKS);
    __shared__ float lsum_s[128];

    const int t    = threadIdx.x;
    const int lane = t & 31;
    const int wid  = t >> 5;
    const int grp  = lane >> 2;
    const int tig  = lane & 3;
    const int wm   = wid >> 2;
    const int wn   = wid & 3;
    const int qt = blockIdx.x, h = blockIdx.y, b = blockIdx.z;
    const int bh = b * HH + h;
    const int qbase = qt * 128;

    if (t < 128) lsum_s[t] = 0.f;

    // stage Q (128 x 64 halves = 128 x 32 h2) — uint4 = 8 halves
    const uint4* Qg4 = (const uint4*)(qg + ((size_t)bh * SS + qbase) * HD);
#pragma unroll
    for (int i = 0; i < 4; i++) {
        const int f = t + 256 * i;           // 0..1023
        const int r = f >> 3, c8 = (f & 7) * 4;
        *(uint4*)&Qs[r][c8] = Qg4[(size_t)r * 8 + (f & 7)];
    }

    const uint4* Kg4 = (const uint4*)(kg + (size_t)bh * SS * HD);
    float rs[4][2];
#pragma unroll
    for (int mt = 0; mt < 4; mt++) { rs[mt][0] = 0.f; rs[mt][1] = 0.f; }

    uint32_t* eg2 = (uint32_t*)eg;

#pragma unroll 1
    for (int kt = 0; kt < 8; kt++) {
        __syncthreads();   // prev MMA reads done (covers Q stage + lsum_s init at kt=0)
#pragma unroll
        for (int i = 0; i < 4; i++) {
            const int f = t + 256 * i;
            const int r = f >> 3, c8 = (f & 7) * 4;
            *(uint4*)&Ks[r][c8] = Kg4[(size_t)(kt * 128 + r) * 8 + (f & 7)];
        }
        __syncthreads();

        float acc[4][4][4];
#pragma unroll
        for (int mt = 0; mt < 4; mt++)
#pragma unroll
            for (int nt = 0; nt < 4; nt++)
#pragma unroll
                for (int r = 0; r < 4; r++) acc[mt][nt][r] = 0.f;

#pragma unroll
        for (int k16 = 0; k16 < 4; k16++) {
            const int ks2 = 8 * k16;           // h2 offset
            uint32_t a[4][4], bq[4][2];
#pragma unroll
            for (int mt = 0; mt < 4; mt++) {
                const int m = wm * 64 + mt * 16;
                a[mt][0] = Qs[m + grp][ks2 + tig];
                a[mt][1] = Qs[m + grp + 8][ks2 + tig];
                a[mt][2] = Qs[m + grp][ks2 + tig + 4];
                a[mt][3] = Qs[m + grp + 8][ks2 + tig + 4];
            }
#pragma unroll
            for (int nt = 0; nt < 4; nt++) {
                const int n = wn * 32 + nt * 8;
                bq[nt][0] = Ks[n + grp][ks2 + tig];
                bq[nt][1] = Ks[n + grp][ks2 + tig + 4];
            }
#pragma unroll
            for (int mt = 0; mt < 4; mt++)
#pragma unroll
                for (int nt = 0; nt < 4; nt++)
                    mma16(acc[mt][nt], a[mt], bq[nt]);
        }

        // epilogue: mask, exp, store e (fp16), accumulate row sums
#pragma unroll
        for (int mt = 0; mt < 4; mt++) {
            const int q0 = qbase + wm * 64 + mt * 16 + grp;
#pragma unroll
            for (int nt = 0; nt < 4; nt++) {
                const int c = kt * 128 + wn * 32 + nt * 8 + 2 * tig;
                const uint2 ma = *(const uint2*)&mask[((size_t)b * SS + q0) * SS + c];
                const uint2 mb = *(const uint2*)&mask[((size_t)b * SS + q0 + 8) * SS + c];
                const float e00 = ma.x ? 0.f : __expf(acc[mt][nt][0] * 0.125f);
                const float e01 = ma.y ? 0.f : __expf(acc[mt][nt][1] * 0.125f);
                const float e10 = mb.x ? 0.f : __expf(acc[mt][nt][2] * 0.125f);
                const float e11 = mb.y ? 0.f : __expf(acc[mt][nt][3] * 0.125f);
                rs[mt][0] += e00 + e01;
                rs[mt][1] += e10 + e11;
                eg2[((size_t)bh * SS + q0) * (SS / 2) + (c >> 1)]     = pack_h2(e00, e01);
                eg2[((size_t)bh * SS + q0 + 8) * (SS / 2) + (c >> 1)] = pack_h2(e10, e11);
            }
        }
    }

    // reduce row sums: quad shuffle then smem atomics (4 n-warps share rows)
#pragma unroll
    for (int mt = 0; mt < 4; mt++)
#pragma unroll
        for (int rr = 0; rr < 2; rr++) {
            float v = rs[mt][rr];
            v += __shfl_xor_sync(0xffffffffu, v, 1);
            v += __shfl_xor_sync(0xffffffffu, v, 2);
            if (tig == 0)
                atomicAdd(&lsum_s[wm * 64 + mt * 16 + grp + 8 * rr], v);
        }
    __syncthreads();
    if (t < 128) lsum[(size_t)bh * SS + qbase + t] = lsum_s[t];
}

// ---------------------------------------------------------------------------
// PV (fp16 MMA): blend p = c0*e/l + l1*rel -> prob (fp32, mandatory output),
// stage P as fp16, O = P @ V with V from d-major fp16 g_vT.
// kt loop: 8 chunks of 128 keys.
// SMEM: Ps[128][68] + Vs[64][68] half2-units = 52.2 KB.
// ---------------------------------------------------------------------------
#define PVS 68
#define PV_SMEM ((128 + 64) * PVS * 4)

__global__ __launch_bounds__(256) void pv_mma(
    const float* __restrict__ lsum, const float* __restrict__ relattn,
    const __half* __restrict__ vT, const __half* __restrict__ eg,
    const float* __restrict__ l1p,
    float* __restrict__ out, float* __restrict__ prob)
{
    extern __shared__ uint32_t psm[];
    uint32_t (*Ps)[PVS] = (uint32_t(*)[PVS])psm;               // [128 q][64 h2 keys + pad]
    uint32_t (*Vs)[PVS] = (uint32_t(*)[PVS])(psm + 128 * PVS); // [64 d][64 h2 keys + pad]
    __shared__ float invl_s[128];

    const int t    = threadIdx.x;
    const int lane = t & 31;
    const int wid  = t >> 5;
    const int grp  = lane >> 2;
    const int tig  = lane & 3;
    const int wm   = wid >> 2;
    const int wn   = wid & 3;
    const int qt = blockIdx.x, h = blockIdx.y, b = blockIdx.z;
    const int bh = b * HH + h;
    const int qbase = qt * 128;

    const float l1 = *l1p;
    const float c0 = 1.f - l1;

    if (t < 128) invl_s[t] = 1.f / lsum[(size_t)bh * SS + qbase + t];
    __syncthreads();

    const uint4* eg4 = (const uint4*)eg;
    const uint4* vT4 = (const uint4*)vT;

    float acc[4][2][4];
#pragma unroll
    for (int mt = 0; mt < 4; mt++)
#pragma unroll
        for (int nt = 0; nt < 2; nt++)
#pragma unroll
            for (int r = 0; r < 4; r++) acc[mt][nt][r] = 0.f;

#pragma unroll 1
    for (int kt = 0; kt < 8; kt++) {
        if (kt) __syncthreads();
        // blend + prob write + stage P (128 q x 128 keys)
#pragma unroll
        for (int i = 0; i < 8; i++) {
            const int f = t + 256 * i;            // 0..2047
            const int r = f >> 4, c16 = (f & 15) * 4;   // h2 col 0..60
            const uint4 e4 = eg4[((size_t)bh * SS + qbase + r) * (SS / 8) + kt * 16 + (f & 15)];
            const float2 e0 = unpack_h2(e4.x);
            const float2 e1 = unpack_h2(e4.y);
            const float2 e2 = unpack_h2(e4.z);
            const float2 e3 = unpack_h2(e4.w);
            const float iv = invl_s[r];
            const float* rrow = relattn + ((size_t)b * SS + qbase + r) * SS + kt * 128 + c16 * 2;
            const float4 r0 = *(const float4*)rrow;
            const float4 r1 = *(const float4*)(rrow + 4);
            float4 p0, p1;
            p0.x = c0 * e0.x * iv + l1 * r0.x;
            p0.y = c0 * e0.y * iv + l1 * r0.y;
            p0.z = c0 * e1.x * iv + l1 * r0.z;
            p0.w = c0 * e1.y * iv + l1 * r0.w;
            p1.x = c0 * e2.x * iv + l1 * r1.x;
            p1.y = c0 * e2.y * iv + l1 * r1.y;
            p1.z = c0 * e3.x * iv + l1 * r1.z;
            p1.w = c0 * e3.y * iv + l1 * r1.w;
            float* prow = prob + ((size_t)bh * SS + qbase + r) * SS + kt * 128 + c16 * 2;
            *(float4*)prow       = p0;
            *(float4*)(prow + 4) = p1;
            uint4 ph;
            ph.x = pack_h2(p0.x, p0.y); ph.y = pack_h2(p0.z, p0.w);
            ph.z = pack_h2(p1.x, p1.y); ph.w = pack_h2(p1.z, p1.w);
            *(uint4*)&Ps[r][c16] = ph;
        }
        // stage V chunk: [64 d][128 keys]
#pragma unroll
        for (int i = 0; i < 4; i++) {
            const int f = t + 256 * i;            // 0..1023
            const int d = f >> 4, c16 = (f & 15) * 4;
            *(uint4*)&Vs[d][c16] =
                vT4[((size_t)bh * HD + d) * (SS / 8) + kt * 16 + (f & 15)];
        }
        __syncthreads();

#pragma unroll
        for (int k16 = 0; k16 < 8; k16++) {
            const int ks2 = 8 * k16;
            uint32_t a[4][4], bq[2][2];
#pragma unroll
            for (int mt = 0; mt < 4; mt++) {
                const int m = wm * 64 + mt * 16;
                a[mt][0] = Ps[m + grp][ks2 + tig];
                a[mt][1] = Ps[m + grp + 8][ks2 + tig];
                a[mt][2] = Ps[m + grp][ks2 + tig + 4];
                a[mt][3] = Ps[m + grp + 8][ks2 + tig + 4];
            }
#pragma unroll
            for (int nt = 0; nt < 2; nt++) {
                const int n = wn * 16 + nt * 8;
                bq[nt][0] = Vs[n + grp][ks2 + tig];
                bq[nt][1] = Vs[n + grp][ks2 + tig + 4];
            }
#pragma unroll
            for (int mt = 0; mt < 4; mt++)
#pragma unroll
                for (int nt = 0; nt < 2; nt++)
                    mma16(acc[mt][nt], a[mt], bq[nt]);
        }
    }

#pragma unroll
    for (int mt = 0; mt < 4; mt++) {
        const int q0 = qbase + wm * 64 + mt * 16 + grp;
#pragma unroll
        for (int nt = 0; nt < 2; nt++) {
            const int d0 = wn * 16 + nt * 8 + 2 * tig;
            *(float2*)&out[((size_t)b * SS + q0) * DD + h * HD + d0] =
                make_float2(acc[mt][nt][0], acc[mt][nt][1]);
            *(float2*)&out[((size_t)b * SS + q0 + 8) * DD + h * HD + d0] =
                make_float2(acc[mt][nt][2], acc[mt][nt][3]);
        }
    }
}

// ---------------------------------------------------------------------------
extern "C" void kernel_launch(void* const* d_in, const int* in_sizes, int n_in,
                              void* d_out, int out_size)
{
    const float* query = (const float*)d_in[0];
    const float* key_t = (const float*)d_in[1];
    const float* value = (const float*)d_in[2];
    const float* rel   = (const float*)d_in[3];
    const unsigned int* mask = (const unsigned int*)d_in[4];
    const float* l1    = (const float*)d_in[5];
    const float* Wq = (const float*)d_in[6];
    const float* bq = (const float*)d_in[7];
    const float* Wk = (const float*)d_in[8];
    const float* bk = (const float*)d_in[9];
    const float* Wv = (const float*)d_in[10];
    const float* bv = (const float*)d_in[11];

    float* out  = (float*)d_out;
    float* prob = out + (size_t)BB * SS * DD;   // tuple layout: out, then prob_attn

    __half *pq, *pk, *pvT, *pe;
    float *prel, *pl;
    cudaGetSymbolAddress((void**)&pq,   g_q);
    cudaGetSymbolAddress((void**)&pk,   g_k);
    cudaGetSymbolAddress((void**)&pvT,  g_vT);
    cudaGetSymbolAddress((void**)&pe,   g_e);
    cudaGetSymbolAddress((void**)&prel, g_rel);
    cudaGetSymbolAddress((void**)&pl,   g_l);

    dim3 pg(DD / 128, (BB * SS) / 128);
    proj_mma<<<pg, 256>>>(query, Wq, bq, pq,  0);
    proj_mma<<<pg, 256>>>(key_t, Wk, bk, pk,  0);
    proj_mma<<<pg, 256>>>(value, Wv, bv, pvT, 1);

    rel_softmax_kernel<<<BB * SS, 256>>>(rel, mask, prel);

    qk_mma<<<dim3(8, HH, BB), 256, QK_SMEM>>>(pq, pk, mask, pe, pl);

    cudaFuncSetAttribute(pv_mma,
                         cudaFuncAttributeMaxDynamicSharedMemorySize, PV_SMEM);
    pv_mma<<<dim3(8, HH, BB), 256, PV_SMEM>>>(pl, prel, pvT, pe, l1, out, prob);
}